// round 1
// baseline (speedup 1.0000x reference)
#include <cuda_runtime.h>
#include <cuda_bf16.h>

// Problem constants
#define B_  64
#define T_  512
#define D_  128
#define R_  2048
static constexpr float HSTEP = 0.5f;
static constexpr float CLAMP_ = 5.0f;

// Scratch: proj[B,T,R] = 64*512*2048 floats = 256 MB (device global, allowed)
__device__ float g_proj[(size_t)B_ * T_ * R_];

__device__ __forceinline__ float clampf(float v) {
    return fminf(fmaxf(v, -CLAMP_), CLAMP_);
}

// ---------------------------------------------------------------------------
// Phase 1: input oscillator recurrence. One thread per (b, d). Writes x_in_all.
// ---------------------------------------------------------------------------
__global__ void k_input_osc(const float* __restrict__ inputs,
                            const float* __restrict__ omega,
                            const float* __restrict__ gamma_,
                            const float* __restrict__ alpha,
                            float* __restrict__ x_in_all) {
    int idx = blockIdx.x * blockDim.x + threadIdx.x;  // b*D + d
    int d = idx % D_;
    int b = idx / D_;
    float om  = fabsf(omega[d]);
    float ga  = fabsf(gamma_[d]);
    float al  = alpha[d];
    float om2 = om * om;
    float g2  = 2.0f * ga;
    float x = 0.0f, y = 0.0f;
    const float* inp = inputs + (size_t)b * T_ * D_ + d;
    float*       out = x_in_all + (size_t)b * T_ * D_ + d;
#pragma unroll 4
    for (int t = 0; t < T_; t++) {
        float f  = inp[t * D_];
        float ac = al * f - g2 * y - om2 * x;
        float xn = clampf(x + HSTEP * y);
        float yn = clampf(y + HSTEP * ac);
        x = xn; y = yn;
        out[t * D_] = x;
    }
}

// ---------------------------------------------------------------------------
// Phase 3: reservoir + output oscillator recurrences. One thread per (b, r).
// Reads proj[B,T,R]; writes x_res_all and x_out_all.
// ---------------------------------------------------------------------------
__global__ void k_res_out_osc(const float* __restrict__ proj,
                              const float* __restrict__ r_om, const float* __restrict__ r_ga,
                              const float* __restrict__ r_al,
                              const float* __restrict__ o_om, const float* __restrict__ o_ga,
                              const float* __restrict__ o_al,
                              float* __restrict__ x_res_all,
                              float* __restrict__ x_out_all) {
    int idx = blockIdx.x * blockDim.x + threadIdx.x;  // b*R + r
    int r = idx % R_;
    int b = idx / R_;
    float rom = fabsf(r_om[r]), rga = fabsf(r_ga[r]), ral = r_al[r];
    float oom = fabsf(o_om[r]), oga = fabsf(o_ga[r]), oal = o_al[r];
    float rom2 = rom * rom, rg2 = 2.0f * rga;
    float oom2 = oom * oom, og2 = 2.0f * oga;
    float xr = 0.0f, yr = 0.0f, xo = 0.0f, yo = 0.0f;
    const float* p   = proj      + (size_t)b * T_ * R_ + r;
    float*       xra = x_res_all + (size_t)b * T_ * R_ + r;
    float*       xoa = x_out_all + (size_t)b * T_ * R_ + r;
#pragma unroll 2
    for (int t = 0; t < T_; t++) {
        float f   = p[t * R_];
        float acr = ral * f - rg2 * yr - rom2 * xr;
        float xrn = clampf(xr + HSTEP * yr);
        float yrn = clampf(yr + HSTEP * acr);
        xr = xrn; yr = yrn;
        float aco = oal * xr - og2 * yo - oom2 * xo;
        float xon = clampf(xo + HSTEP * yo);
        float yon = clampf(yo + HSTEP * aco);
        xo = xon; yo = yon;
        xra[t * R_] = xr;
        xoa[t * R_] = xo;
    }
}

// ---------------------------------------------------------------------------
// Generic fp32 GEMM with bias: C[M,N] = A[M,K] @ B[K,N] + bias[N]
// A row-major [M,K], B row-major [K,N]. All dims divisible by tile sizes.
// BM=64, BN=64, BK=16, 256 threads, 4x4 per thread.
// ---------------------------------------------------------------------------
__global__ __launch_bounds__(256) void sgemm_bias(const float* __restrict__ A,
                                                  const float* __restrict__ Bm,
                                                  const float* __restrict__ bias,
                                                  float* __restrict__ C,
                                                  int M, int N, int K) {
    constexpr int BM = 64, BN = 64, BK = 16, TM = 4, TN = 4;
    __shared__ float As[BK][BM + 4];
    __shared__ float Bs[BK][BN];

    int tid = threadIdx.x;
    int tn  = tid % (BN / TN);  // 0..15 (n group)
    int tm  = tid / (BN / TN);  // 0..15 (m group)
    int rowBase = blockIdx.y * BM;
    int colBase = blockIdx.x * BN;

    // A tile load mapping: 64 rows x 16 k, one float4 along K per thread
    int aRow  = tid / (BK / 4);        // 0..63
    int aCol4 = (tid % (BK / 4)) * 4;  // 0,4,8,12
    // B tile load mapping: 16 rows x 64 n, one float4 along N per thread
    int bRow  = tid / (BN / 4);        // 0..15
    int bCol4 = (tid % (BN / 4)) * 4;

    float acc[TM][TN] = {};

    const float* Aptr = A + (size_t)(rowBase + aRow) * K + aCol4;
    const float* Bptr = Bm + (size_t)bRow * N + colBase + bCol4;

    for (int k0 = 0; k0 < K; k0 += BK) {
        float4 av = *(const float4*)(Aptr + k0);
        float4 bv = *(const float4*)(Bptr + (size_t)k0 * N);
        As[aCol4 + 0][aRow] = av.x;
        As[aCol4 + 1][aRow] = av.y;
        As[aCol4 + 2][aRow] = av.z;
        As[aCol4 + 3][aRow] = av.w;
        *(float4*)&Bs[bRow][bCol4] = bv;
        __syncthreads();
#pragma unroll
        for (int k = 0; k < BK; k++) {
            float ra[TM], rb[TN];
#pragma unroll
            for (int i = 0; i < TM; i++) ra[i] = As[k][tm * TM + i];
#pragma unroll
            for (int j = 0; j < TN; j++) rb[j] = Bs[k][tn * TN + j];
#pragma unroll
            for (int i = 0; i < TM; i++)
#pragma unroll
                for (int j = 0; j < TN; j++) acc[i][j] += ra[i] * rb[j];
        }
        __syncthreads();
    }

    // Epilogue with bias
    int col0 = colBase + tn * TN;
    float4 bz = *(const float4*)&bias[col0];
#pragma unroll
    for (int i = 0; i < TM; i++) {
        int row = rowBase + tm * TM + i;
        float4 o;
        o.x = acc[i][0] + bz.x;
        o.y = acc[i][1] + bz.y;
        o.z = acc[i][2] + bz.z;
        o.w = acc[i][3] + bz.w;
        *(float4*)&C[(size_t)row * N + col0] = o;
    }
}

// ---------------------------------------------------------------------------
// Launch: 4 kernels on the default stream (stream order = dependency order).
// Output layout (reference tuple order): preds | x_in_all | x_res_all | x_out_all
// ---------------------------------------------------------------------------
extern "C" void kernel_launch(void* const* d_in, const int* in_sizes, int n_in,
                              void* d_out, int out_size) {
    const float* inputs   = (const float*)d_in[0];
    const float* in_omega = (const float*)d_in[1];
    const float* in_gamma = (const float*)d_in[2];
    const float* in_alpha = (const float*)d_in[3];
    const float* proj_W   = (const float*)d_in[4];
    const float* proj_b   = (const float*)d_in[5];
    const float* res_om   = (const float*)d_in[6];
    const float* res_ga   = (const float*)d_in[7];
    const float* res_al   = (const float*)d_in[8];
    const float* out_om   = (const float*)d_in[9];
    const float* out_ga   = (const float*)d_in[10];
    const float* out_al   = (const float*)d_in[11];
    const float* read_W   = (const float*)d_in[12];
    const float* read_b   = (const float*)d_in[13];

    float* out = (float*)d_out;
    const size_t BTD = (size_t)B_ * T_ * D_;   // 4,194,304
    const size_t BTR = (size_t)B_ * T_ * R_;   // 67,108,864
    float* preds     = out;
    float* x_in_all  = out + BTD;
    float* x_res_all = out + 2 * BTD;
    float* x_out_all = out + 2 * BTD + BTR;

    void* proj_ptr = nullptr;
    cudaGetSymbolAddress(&proj_ptr, g_proj);
    float* proj = (float*)proj_ptr;

    // Phase 1: input oscillators (B*D = 8192 threads)
    k_input_osc<<<(B_ * D_) / 256, 256>>>(inputs, in_omega, in_gamma, in_alpha, x_in_all);

    // Phase 2: proj[B*T, R] = x_in_all[B*T, D] @ proj_W[D, R] + proj_b
    {
        dim3 grid(R_ / 64, (B_ * T_) / 64);  // (32, 512)
        sgemm_bias<<<grid, 256>>>(x_in_all, proj_W, proj_b, proj, B_ * T_, R_, D_);
    }

    // Phase 3: reservoir + output oscillators (B*R = 131072 threads)
    k_res_out_osc<<<(B_ * R_) / 256, 256>>>(proj, res_om, res_ga, res_al,
                                            out_om, out_ga, out_al,
                                            x_res_all, x_out_all);

    // Phase 4: preds[B*T, D] = x_out_all[B*T, R] @ read_W[R, D] + read_b
    {
        dim3 grid(D_ / 64, (B_ * T_) / 64);  // (2, 512)
        sgemm_bias<<<grid, 256>>>(x_out_all, read_W, read_b, preds, B_ * T_, D_, R_);
    }
}

// round 2
// speedup vs baseline: 1.1272x; 1.1272x over previous
#include <cuda_runtime.h>
#include <cuda_bf16.h>

// Problem constants
#define B_  64
#define T_  512
#define D_  128
#define R_  2048
static constexpr float HSTEP = 0.5f;
static constexpr float CLAMP_ = 5.0f;

// Scratch: proj[B,T,R] = 64*512*2048 floats = 256 MB (device global, allowed)
__device__ float g_proj[(size_t)B_ * T_ * R_];

__device__ __forceinline__ float clampf(float v) {
    return fminf(fmaxf(v, -CLAMP_), CLAMP_);
}

// ---------------------------------------------------------------------------
// Phase 1: input oscillator recurrence. One thread per (b, d). Writes x_in_all.
// ---------------------------------------------------------------------------
__global__ void k_input_osc(const float* __restrict__ inputs,
                            const float* __restrict__ omega,
                            const float* __restrict__ gamma_,
                            const float* __restrict__ alpha,
                            float* __restrict__ x_in_all) {
    int idx = blockIdx.x * blockDim.x + threadIdx.x;  // b*D + d
    int d = idx % D_;
    int b = idx / D_;
    float om  = fabsf(omega[d]);
    float ga  = fabsf(gamma_[d]);
    float al  = alpha[d];
    float om2 = om * om;
    float g2  = 2.0f * ga;
    float x = 0.0f, y = 0.0f;
    const float* inp = inputs + (size_t)b * T_ * D_ + d;
    float*       out = x_in_all + (size_t)b * T_ * D_ + d;
#pragma unroll 4
    for (int t = 0; t < T_; t++) {
        float f  = inp[t * D_];
        float ac = al * f - g2 * y - om2 * x;
        float xn = clampf(x + HSTEP * y);
        float yn = clampf(y + HSTEP * ac);
        x = xn; y = yn;
        out[t * D_] = x;
    }
}

// ---------------------------------------------------------------------------
// Phase 3: reservoir + output oscillators, float4-vectorized over r.
// One thread per (b, r4-group of 4). Reads proj; writes x_res_all, x_out_all.
// ---------------------------------------------------------------------------
__global__ void k_res_out_osc_v4(const float4* __restrict__ proj,
                                 const float4* __restrict__ r_om, const float4* __restrict__ r_ga,
                                 const float4* __restrict__ r_al,
                                 const float4* __restrict__ o_om, const float4* __restrict__ o_ga,
                                 const float4* __restrict__ o_al,
                                 float4* __restrict__ x_res_all,
                                 float4* __restrict__ x_out_all) {
    constexpr int R4 = R_ / 4;  // 512
    int idx = blockIdx.x * blockDim.x + threadIdx.x;  // b*R4 + r4
    int r4 = idx % R4;
    int b  = idx / R4;

    float4 romv = r_om[r4], rgav = r_ga[r4], ralv = r_al[r4];
    float4 oomv = o_om[r4], ogav = o_ga[r4], oalv = o_al[r4];
    float rom2[4], rg2[4], ral[4], oom2[4], og2[4], oal[4];
    {
        const float* p;
        p = &romv.x; for (int i = 0; i < 4; i++) { float v = fabsf(p[i]); rom2[i] = v * v; }
        p = &rgav.x; for (int i = 0; i < 4; i++) rg2[i] = 2.0f * fabsf(p[i]);
        p = &ralv.x; for (int i = 0; i < 4; i++) ral[i] = p[i];
        p = &oomv.x; for (int i = 0; i < 4; i++) { float v = fabsf(p[i]); oom2[i] = v * v; }
        p = &ogav.x; for (int i = 0; i < 4; i++) og2[i] = 2.0f * fabsf(p[i]);
        p = &oalv.x; for (int i = 0; i < 4; i++) oal[i] = p[i];
    }

    float xr[4] = {}, yr[4] = {}, xo[4] = {}, yo[4] = {};
    const float4* pp  = proj      + (size_t)b * T_ * R4 + r4;
    float4*       xra = x_res_all + (size_t)b * T_ * R4 + r4;
    float4*       xoa = x_out_all + (size_t)b * T_ * R4 + r4;

#pragma unroll 2
    for (int t = 0; t < T_; t++) {
        float4 fv = pp[t * R4];
        float f[4] = {fv.x, fv.y, fv.z, fv.w};
        float4 xro, xoo;
        float* xrp = &xro.x;
        float* xop = &xoo.x;
#pragma unroll
        for (int i = 0; i < 4; i++) {
            float acr = ral[i] * f[i] - rg2[i] * yr[i] - rom2[i] * xr[i];
            float xrn = clampf(xr[i] + HSTEP * yr[i]);
            float yrn = clampf(yr[i] + HSTEP * acr);
            xr[i] = xrn; yr[i] = yrn;
            float aco = oal[i] * xr[i] - og2[i] * yo[i] - oom2[i] * xo[i];
            float xon = clampf(xo[i] + HSTEP * yo[i]);
            float yon = clampf(yo[i] + HSTEP * aco);
            xo[i] = xon; yo[i] = yon;
            xrp[i] = xr[i];
            xop[i] = xo[i];
        }
        xra[t * R4] = xro;
        xoa[t * R4] = xoo;
    }
}

// ---------------------------------------------------------------------------
// fp32 GEMM with bias: C[M,N] = A[M,K] @ B[K,N] + bias[N]
// BM=BN=128, BK=16, 256 threads, 8x8 microtile, smem double-buffered,
// register-prefetched global loads. M%128==0, N%128==0, K%16==0.
// ---------------------------------------------------------------------------
__global__ __launch_bounds__(256, 2) void sgemm_bias_v2(const float* __restrict__ A,
                                                        const float* __restrict__ Bm,
                                                        const float* __restrict__ bias,
                                                        float* __restrict__ C,
                                                        int M, int N, int K) {
    constexpr int BM = 128, BN = 128, BK = 16;
    __shared__ float As[2][BK][BM + 4];
    __shared__ float Bs[2][BK][BN];

    const int tid = threadIdx.x;
    const int rowBase = blockIdx.y * BM;
    const int colBase = blockIdx.x * BN;

    // Global->smem load mapping
    const int aRow = tid >> 2;          // 0..63 (and +64)
    const int aCol = (tid & 3) * 4;     // 0,4,8,12 along K
    const int bRow = tid >> 5;          // 0..7 (and +8) along K
    const int bCol = (tid & 31) * 4;    // 0..124 along N

    const float* Aptr0 = A + (size_t)(rowBase + aRow) * K + aCol;
    const float* Aptr1 = Aptr0 + (size_t)64 * K;
    const float* Bptr0 = Bm + (size_t)bRow * N + colBase + bCol;
    const float* Bptr1 = Bptr0 + (size_t)8 * N;

    // Compute mapping: 8x8 per thread
    const int tm = (tid >> 4) * 8;      // 0..120
    const int tn = (tid & 15) * 8;      // 0..120

    float acc[8][8] = {};
    float4 pa0, pa1, pb0, pb1;

    // Prologue: load tile 0
    pa0 = *(const float4*)(Aptr0);
    pa1 = *(const float4*)(Aptr1);
    pb0 = *(const float4*)(Bptr0);
    pb1 = *(const float4*)(Bptr1);
    {
        As[0][aCol + 0][aRow] = pa0.x;
        As[0][aCol + 1][aRow] = pa0.y;
        As[0][aCol + 2][aRow] = pa0.z;
        As[0][aCol + 3][aRow] = pa0.w;
        As[0][aCol + 0][aRow + 64] = pa1.x;
        As[0][aCol + 1][aRow + 64] = pa1.y;
        As[0][aCol + 2][aRow + 64] = pa1.z;
        As[0][aCol + 3][aRow + 64] = pa1.w;
        *(float4*)&Bs[0][bRow][bCol] = pb0;
        *(float4*)&Bs[0][bRow + 8][bCol] = pb1;
    }
    __syncthreads();

    int buf = 0;
    for (int k0 = 0; k0 < K; k0 += BK) {
        const int knext = k0 + BK;
        if (knext < K) {
            pa0 = *(const float4*)(Aptr0 + knext);
            pa1 = *(const float4*)(Aptr1 + knext);
            pb0 = *(const float4*)(Bptr0 + (size_t)knext * N);
            pb1 = *(const float4*)(Bptr1 + (size_t)knext * N);
        }
#pragma unroll
        for (int k = 0; k < BK; k++) {
            float4 ra0 = *(const float4*)&As[buf][k][tm];
            float4 ra1 = *(const float4*)&As[buf][k][tm + 4];
            float4 rb0 = *(const float4*)&Bs[buf][k][tn];
            float4 rb1 = *(const float4*)&Bs[buf][k][tn + 4];
            float ra[8] = {ra0.x, ra0.y, ra0.z, ra0.w, ra1.x, ra1.y, ra1.z, ra1.w};
            float rb[8] = {rb0.x, rb0.y, rb0.z, rb0.w, rb1.x, rb1.y, rb1.z, rb1.w};
#pragma unroll
            for (int i = 0; i < 8; i++)
#pragma unroll
                for (int j = 0; j < 8; j++) acc[i][j] += ra[i] * rb[j];
        }
        if (knext < K) {
            int nb = buf ^ 1;
            As[nb][aCol + 0][aRow] = pa0.x;
            As[nb][aCol + 1][aRow] = pa0.y;
            As[nb][aCol + 2][aRow] = pa0.z;
            As[nb][aCol + 3][aRow] = pa0.w;
            As[nb][aCol + 0][aRow + 64] = pa1.x;
            As[nb][aCol + 1][aRow + 64] = pa1.y;
            As[nb][aCol + 2][aRow + 64] = pa1.z;
            As[nb][aCol + 3][aRow + 64] = pa1.w;
            *(float4*)&Bs[nb][bRow][bCol] = pb0;
            *(float4*)&Bs[nb][bRow + 8][bCol] = pb1;
            __syncthreads();
            buf = nb;
        }
    }

    // Epilogue with bias
    const int col0 = colBase + tn;
    float4 bz0 = *(const float4*)&bias[col0];
    float4 bz1 = *(const float4*)&bias[col0 + 4];
#pragma unroll
    for (int i = 0; i < 8; i++) {
        int row = rowBase + tm + i;
        float4 o0, o1;
        o0.x = acc[i][0] + bz0.x;
        o0.y = acc[i][1] + bz0.y;
        o0.z = acc[i][2] + bz0.z;
        o0.w = acc[i][3] + bz0.w;
        o1.x = acc[i][4] + bz1.x;
        o1.y = acc[i][5] + bz1.y;
        o1.z = acc[i][6] + bz1.z;
        o1.w = acc[i][7] + bz1.w;
        *(float4*)&C[(size_t)row * N + col0] = o0;
        *(float4*)&C[(size_t)row * N + col0 + 4] = o1;
    }
}

// ---------------------------------------------------------------------------
// Launch: 4 kernels on the default stream (stream order = dependency order).
// Output layout (reference tuple order): preds | x_in_all | x_res_all | x_out_all
// ---------------------------------------------------------------------------
extern "C" void kernel_launch(void* const* d_in, const int* in_sizes, int n_in,
                              void* d_out, int out_size) {
    const float* inputs   = (const float*)d_in[0];
    const float* in_omega = (const float*)d_in[1];
    const float* in_gamma = (const float*)d_in[2];
    const float* in_alpha = (const float*)d_in[3];
    const float* proj_W   = (const float*)d_in[4];
    const float* proj_b   = (const float*)d_in[5];
    const float* res_om   = (const float*)d_in[6];
    const float* res_ga   = (const float*)d_in[7];
    const float* res_al   = (const float*)d_in[8];
    const float* out_om   = (const float*)d_in[9];
    const float* out_ga   = (const float*)d_in[10];
    const float* out_al   = (const float*)d_in[11];
    const float* read_W   = (const float*)d_in[12];
    const float* read_b   = (const float*)d_in[13];

    float* out = (float*)d_out;
    const size_t BTD = (size_t)B_ * T_ * D_;   // 4,194,304
    const size_t BTR = (size_t)B_ * T_ * R_;   // 67,108,864
    float* preds     = out;
    float* x_in_all  = out + BTD;
    float* x_res_all = out + 2 * BTD;
    float* x_out_all = out + 2 * BTD + BTR;

    void* proj_ptr = nullptr;
    cudaGetSymbolAddress(&proj_ptr, g_proj);
    float* proj = (float*)proj_ptr;

    // Phase 1: input oscillators (B*D = 8192 threads)
    k_input_osc<<<(B_ * D_) / 256, 256>>>(inputs, in_omega, in_gamma, in_alpha, x_in_all);

    // Phase 2: proj[B*T, R] = x_in_all[B*T, D] @ proj_W[D, R] + proj_b
    {
        dim3 grid(R_ / 128, (B_ * T_) / 128);  // (16, 256)
        sgemm_bias_v2<<<grid, 256>>>(x_in_all, proj_W, proj_b, proj, B_ * T_, R_, D_);
    }

    // Phase 3: reservoir + output oscillators (B*R/4 = 32768 threads, float4)
    k_res_out_osc_v4<<<(B_ * R_ / 4) / 128, 128>>>((const float4*)proj,
                                                   (const float4*)res_om, (const float4*)res_ga,
                                                   (const float4*)res_al,
                                                   (const float4*)out_om, (const float4*)out_ga,
                                                   (const float4*)out_al,
                                                   (float4*)x_res_all, (float4*)x_out_all);

    // Phase 4: preds[B*T, D] = x_out_all[B*T, R] @ read_W[R, D] + read_b
    {
        dim3 grid(D_ / 128, (B_ * T_) / 128);  // (1, 256)
        sgemm_bias_v2<<<grid, 256>>>(x_out_all, read_W, read_b, preds, B_ * T_, D_, R_);
    }
}

// round 5
// speedup vs baseline: 1.3719x; 1.2171x over previous
#include <cuda_runtime.h>
#include <cuda_bf16.h>
#include <cstdint>

// Problem constants
#define B_  64
#define T_  512
#define D_  128
#define R_  2048
static constexpr float HSTEP = 0.5f;
static constexpr float CLAMP_ = 5.0f;

// Device scratch
__device__ float g_proj[(size_t)B_ * T_ * R_];                 // 256 MB
__device__ __nv_bfloat16 g_B2h[(size_t)D_ * R_];               // read_W planes [N=128, K=2048]
__device__ __nv_bfloat16 g_B2l[(size_t)D_ * R_];

__device__ __forceinline__ float clampf(float v) {
    return fminf(fmaxf(v, -CLAMP_), CLAMP_);
}

// ---------------------------------------------------------------------------
// Baseline-PTX helpers (bench ptxas targets sm_103: no 'a'-suffix features;
// mma.sync/ldmatrix/cp.async only)
// ---------------------------------------------------------------------------
__device__ __forceinline__ uint32_t smem_u32(const void* p) {
    uint32_t a;
    asm("{ .reg .u64 t; cvta.to.shared.u64 t, %1; cvt.u32.u64 %0, t; }" : "=r"(a) : "l"(p));
    return a;
}
__device__ __forceinline__ void cp_async16(uint32_t dst, const void* src) {
    asm volatile("cp.async.ca.shared.global [%0], [%1], 16;" :: "r"(dst), "l"(src) : "memory");
}
#define CP_COMMIT() asm volatile("cp.async.commit_group;" ::: "memory")
#define CP_WAIT(n)  asm volatile("cp.async.wait_group %0;" :: "n"(n) : "memory")

__device__ __forceinline__ void ldsm_x4(uint32_t addr, uint32_t& r0, uint32_t& r1,
                                        uint32_t& r2, uint32_t& r3) {
    asm volatile("ldmatrix.sync.aligned.m8n8.x4.shared.b16 {%0,%1,%2,%3}, [%4];"
                 : "=r"(r0), "=r"(r1), "=r"(r2), "=r"(r3) : "r"(addr));
}
__device__ __forceinline__ void mma_bf16(float* c, const uint32_t* a, uint32_t b0, uint32_t b1) {
    asm volatile(
        "mma.sync.aligned.m16n8k16.row.col.f32.bf16.bf16.f32 "
        "{%0,%1,%2,%3}, {%4,%5,%6,%7}, {%8,%9}, {%0,%1,%2,%3};"
        : "+f"(c[0]), "+f"(c[1]), "+f"(c[2]), "+f"(c[3])
        : "r"(a[0]), "r"(a[1]), "r"(a[2]), "r"(a[3]), "r"(b0), "r"(b1));
}

#define SWZ(off) ((off) ^ (((off) >> 3) & 0x70))

// ---------------------------------------------------------------------------
// Phase 1: input oscillator recurrence. One thread per (b, d).
// ---------------------------------------------------------------------------
__global__ void k_input_osc(const float* __restrict__ inputs,
                            const float* __restrict__ omega,
                            const float* __restrict__ gamma_,
                            const float* __restrict__ alpha,
                            float* __restrict__ x_in_all) {
    int idx = blockIdx.x * blockDim.x + threadIdx.x;
    int d = idx % D_;
    int b = idx / D_;
    float om  = fabsf(omega[d]);
    float ga  = fabsf(gamma_[d]);
    float al  = alpha[d];
    float om2 = om * om;
    float g2  = 2.0f * ga;
    float x = 0.0f, y = 0.0f;
    const float* inp = inputs + (size_t)b * T_ * D_ + d;
    float*       out = x_in_all + (size_t)b * T_ * D_ + d;
#pragma unroll 4
    for (int t = 0; t < T_; t++) {
        float f  = inp[t * D_];
        float ac = al * f - g2 * y - om2 * x;
        float xn = clampf(x + HSTEP * y);
        float yn = clampf(y + HSTEP * ac);
        x = xn; y = yn;
        out[t * D_] = x;
    }
}

// ---------------------------------------------------------------------------
// Weight split + transpose: W [K,N] fp32 row-major -> Dh/Dl [N,K] bf16
// ---------------------------------------------------------------------------
__global__ void k_split_transpose(const float* __restrict__ W,
                                  __nv_bfloat16* __restrict__ Dh,
                                  __nv_bfloat16* __restrict__ Dl,
                                  int K, int N) {
    int idx = blockIdx.x * blockDim.x + threadIdx.x;
    if (idx >= K * N) return;
    int n = idx % N, k = idx / N;
    float v = W[idx];
    __nv_bfloat16 h = __float2bfloat16_rn(v);
    __nv_bfloat16 l = __float2bfloat16_rn(v - __bfloat162float(h));
    Dh[(size_t)n * K + k] = h;
    Dl[(size_t)n * K + k] = l;
}

// ---------------------------------------------------------------------------
// Phase 3: reservoir + output oscillators, float4-vectorized over r.
// ---------------------------------------------------------------------------
__global__ void k_res_out_osc_v4(const float4* __restrict__ proj,
                                 const float4* __restrict__ r_om, const float4* __restrict__ r_ga,
                                 const float4* __restrict__ r_al,
                                 const float4* __restrict__ o_om, const float4* __restrict__ o_ga,
                                 const float4* __restrict__ o_al,
                                 float4* __restrict__ x_res_all,
                                 float4* __restrict__ x_out_all) {
    constexpr int R4 = R_ / 4;
    int idx = blockIdx.x * blockDim.x + threadIdx.x;
    int r4 = idx % R4;
    int b  = idx / R4;

    float4 romv = r_om[r4], rgav = r_ga[r4], ralv = r_al[r4];
    float4 oomv = o_om[r4], ogav = o_ga[r4], oalv = o_al[r4];
    float rom2[4], rg2[4], ral[4], oom2[4], og2[4], oal[4];
    {
        const float* p;
        p = &romv.x; for (int i = 0; i < 4; i++) { float v = fabsf(p[i]); rom2[i] = v * v; }
        p = &rgav.x; for (int i = 0; i < 4; i++) rg2[i] = 2.0f * fabsf(p[i]);
        p = &ralv.x; for (int i = 0; i < 4; i++) ral[i] = p[i];
        p = &oomv.x; for (int i = 0; i < 4; i++) { float v = fabsf(p[i]); oom2[i] = v * v; }
        p = &ogav.x; for (int i = 0; i < 4; i++) og2[i] = 2.0f * fabsf(p[i]);
        p = &oalv.x; for (int i = 0; i < 4; i++) oal[i] = p[i];
    }

    float xr[4] = {}, yr[4] = {}, xo[4] = {}, yo[4] = {};
    const float4* pp  = proj      + (size_t)b * T_ * R4 + r4;
    float4*       xra = x_res_all + (size_t)b * T_ * R4 + r4;
    float4*       xoa = x_out_all + (size_t)b * T_ * R4 + r4;

#pragma unroll 2
    for (int t = 0; t < T_; t++) {
        float4 fv = pp[t * R4];
        float f[4] = {fv.x, fv.y, fv.z, fv.w};
        float4 xro, xoo;
        float* xrp = &xro.x;
        float* xop = &xoo.x;
#pragma unroll
        for (int i = 0; i < 4; i++) {
            float acr = ral[i] * f[i] - rg2[i] * yr[i] - rom2[i] * xr[i];
            float xrn = clampf(xr[i] + HSTEP * yr[i]);
            float yrn = clampf(yr[i] + HSTEP * acr);
            xr[i] = xrn; yr[i] = yrn;
            float aco = oal[i] * xr[i] - og2[i] * yo[i] - oom2[i] * xo[i];
            float xon = clampf(xo[i] + HSTEP * yo[i]);
            float yon = clampf(yo[i] + HSTEP * aco);
            xo[i] = xon; yo[i] = yon;
            xrp[i] = xr[i];
            xop[i] = xo[i];
        }
        xra[t * R4] = xro;
        xoa[t * R4] = xoo;
    }
}

// ---------------------------------------------------------------------------
// fp32 SIMT GEMM (precision-critical path: proj feeds a chaotic recurrence,
// needs fp32-level accuracy). C[M,N] = A[M,K] @ B[K,N] + bias[N].
// BM=BN=128, BK=16, 256 threads, 8x8 microtile, double-buffered smem.
// ---------------------------------------------------------------------------
__global__ __launch_bounds__(256, 2) void sgemm_bias_v2(const float* __restrict__ A,
                                                        const float* __restrict__ Bm,
                                                        const float* __restrict__ bias,
                                                        float* __restrict__ C,
                                                        int M, int N, int K) {
    constexpr int BK = 16;
    __shared__ float As[2][BK][128 + 4];
    __shared__ float Bs[2][BK][128];

    const int tid = threadIdx.x;
    const int rowBase = blockIdx.y * 128;
    const int colBase = blockIdx.x * 128;

    const int aRow = tid >> 2;
    const int aCol = (tid & 3) * 4;
    const int bRow = tid >> 5;
    const int bCol = (tid & 31) * 4;

    const float* Aptr0 = A + (size_t)(rowBase + aRow) * K + aCol;
    const float* Aptr1 = Aptr0 + (size_t)64 * K;
    const float* Bptr0 = Bm + (size_t)bRow * N + colBase + bCol;
    const float* Bptr1 = Bptr0 + (size_t)8 * N;

    const int tm = (tid >> 4) * 8;
    const int tn = (tid & 15) * 8;

    float acc[8][8] = {};
    float4 pa0, pa1, pb0, pb1;

    pa0 = *(const float4*)(Aptr0);
    pa1 = *(const float4*)(Aptr1);
    pb0 = *(const float4*)(Bptr0);
    pb1 = *(const float4*)(Bptr1);
    {
        As[0][aCol + 0][aRow] = pa0.x;
        As[0][aCol + 1][aRow] = pa0.y;
        As[0][aCol + 2][aRow] = pa0.z;
        As[0][aCol + 3][aRow] = pa0.w;
        As[0][aCol + 0][aRow + 64] = pa1.x;
        As[0][aCol + 1][aRow + 64] = pa1.y;
        As[0][aCol + 2][aRow + 64] = pa1.z;
        As[0][aCol + 3][aRow + 64] = pa1.w;
        *(float4*)&Bs[0][bRow][bCol] = pb0;
        *(float4*)&Bs[0][bRow + 8][bCol] = pb1;
    }
    __syncthreads();

    int buf = 0;
    for (int k0 = 0; k0 < K; k0 += BK) {
        const int knext = k0 + BK;
        if (knext < K) {
            pa0 = *(const float4*)(Aptr0 + knext);
            pa1 = *(const float4*)(Aptr1 + knext);
            pb0 = *(const float4*)(Bptr0 + (size_t)knext * N);
            pb1 = *(const float4*)(Bptr1 + (size_t)knext * N);
        }
#pragma unroll
        for (int k = 0; k < BK; k++) {
            float4 ra0 = *(const float4*)&As[buf][k][tm];
            float4 ra1 = *(const float4*)&As[buf][k][tm + 4];
            float4 rb0 = *(const float4*)&Bs[buf][k][tn];
            float4 rb1 = *(const float4*)&Bs[buf][k][tn + 4];
            float ra[8] = {ra0.x, ra0.y, ra0.z, ra0.w, ra1.x, ra1.y, ra1.z, ra1.w};
            float rb[8] = {rb0.x, rb0.y, rb0.z, rb0.w, rb1.x, rb1.y, rb1.z, rb1.w};
#pragma unroll
            for (int i = 0; i < 8; i++)
#pragma unroll
                for (int j = 0; j < 8; j++) acc[i][j] += ra[i] * rb[j];
        }
        if (knext < K) {
            int nb = buf ^ 1;
            As[nb][aCol + 0][aRow] = pa0.x;
            As[nb][aCol + 1][aRow] = pa0.y;
            As[nb][aCol + 2][aRow] = pa0.z;
            As[nb][aCol + 3][aRow] = pa0.w;
            As[nb][aCol + 0][aRow + 64] = pa1.x;
            As[nb][aCol + 1][aRow + 64] = pa1.y;
            As[nb][aCol + 2][aRow + 64] = pa1.z;
            As[nb][aCol + 3][aRow + 64] = pa1.w;
            *(float4*)&Bs[nb][bRow][bCol] = pb0;
            *(float4*)&Bs[nb][bRow + 8][bCol] = pb1;
            __syncthreads();
            buf = nb;
        }
    }

    const int col0 = colBase + tn;
    float4 bz0 = *(const float4*)&bias[col0];
    float4 bz1 = *(const float4*)&bias[col0 + 4];
#pragma unroll
    for (int i = 0; i < 8; i++) {
        int row = rowBase + tm + i;
        float4 o0, o1;
        o0.x = acc[i][0] + bz0.x;
        o0.y = acc[i][1] + bz0.y;
        o0.z = acc[i][2] + bz0.z;
        o0.w = acc[i][3] + bz0.w;
        o1.x = acc[i][4] + bz1.x;
        o1.y = acc[i][5] + bz1.y;
        o1.z = acc[i][6] + bz1.z;
        o1.w = acc[i][7] + bz1.w;
        *(float4*)&C[(size_t)row * N + col0] = o0;
        *(float4*)&C[(size_t)row * N + col0 + 4] = o1;
    }
}

// ---------------------------------------------------------------------------
// Split-bf16 tensor-core GEMM via mma.sync (precision-tolerant readout path):
// C[M,N] = A[M,K](fp32) @ W + bias, W as bf16 hi/lo planes [N,K] K-major.
// CTA 128x128, K-chunks 64, double-buffered; D += Ah*Bh + Ah*Bl + Al*Bh.
// ---------------------------------------------------------------------------
__global__ __launch_bounds__(256) void gemm_mma_split(const float* __restrict__ A,
                                                      const __nv_bfloat16* __restrict__ Bh,
                                                      const __nv_bfloat16* __restrict__ Bl,
                                                      const float* __restrict__ bias,
                                                      float* __restrict__ C,
                                                      int M, int N, int K) {
    extern __shared__ char smem[];
    const int tid  = threadIdx.x;
    const int wid  = tid >> 5;
    const int lane = tid & 31;
    const uint32_t sb = smem_u32(smem);
    const int rowBase = blockIdx.y * 128;
    const int colBase = blockIdx.x * 128;
    const int NCHUNK = K >> 6;

    auto load_chunk = [&](int c, int s) {
        const int k0 = c << 6;
        char* Ah_s = smem + s * 65536;
        char* Al_s = Ah_s + 16384;
        const uint32_t bh_u = sb + s * 65536 + 32768;
        const uint32_t bl_u = bh_u + 16384;
#pragma unroll
        for (int i = 0; i < 4; i++) {
            int u = tid + 256 * i;
            int row = u >> 3;
            int kc = (u & 7) * 8;
            const float4* src = (const float4*)(A + (size_t)(rowBase + row) * K + k0 + kc);
            float4 v0 = src[0], v1 = src[1];
            float vv[8] = {v0.x, v0.y, v0.z, v0.w, v1.x, v1.y, v1.z, v1.w};
            __nv_bfloat16 h[8], l[8];
#pragma unroll
            for (int j = 0; j < 8; j++) {
                h[j] = __float2bfloat16_rn(vv[j]);
                l[j] = __float2bfloat16_rn(vv[j] - __bfloat162float(h[j]));
            }
            uint32_t off = SWZ((uint32_t)(row * 128 + kc * 2));
            *(uint4*)(Ah_s + off) = *(const uint4*)h;
            *(uint4*)(Al_s + off) = *(const uint4*)l;
        }
#pragma unroll
        for (int i = 0; i < 4; i++) {
            int ch = tid + 256 * i;
            int row = ch >> 3;
            int kc16 = ch & 7;
            uint32_t off = SWZ((uint32_t)(row * 128 + kc16 * 16));
            const char* sh = (const char*)(Bh + (size_t)(colBase + row) * K + k0) + kc16 * 16;
            const char* sl = (const char*)(Bl + (size_t)(colBase + row) * K + k0) + kc16 * 16;
            cp_async16(bh_u + off, sh);
            cp_async16(bl_u + off, sl);
        }
    };

    const int warpM = wid & 1;
    const int warpN = wid >> 1;
    const int g = lane >> 3;
    const int r = lane & 7;

    float acc[4][4][4] = {};

    const int aRow = warpM * 64 + (g & 1) * 8 + r;
    const int aKu  = (g >> 1);
    const int bRow = warpN * 32 + (g >> 1) * 8 + r;
    const int bKu  = (g & 1);

    load_chunk(0, 0);
    CP_COMMIT();

    for (int c = 0; c < NCHUNK; c++) {
        const int s = c & 1;
        if (c + 1 < NCHUNK) {
            load_chunk(c + 1, s ^ 1);
            CP_COMMIT();
            CP_WAIT(1);
        } else {
            CP_WAIT(0);
        }
        __syncthreads();

        const uint32_t aH_b = sb + s * 65536;
        const uint32_t aL_b = aH_b + 16384;
        const uint32_t bH_b = aH_b + 32768;
        const uint32_t bL_b = aH_b + 49152;

#pragma unroll
        for (int ks = 0; ks < 4; ks++) {
            uint32_t aH[4][4], aL[4][4];
            const int ku = ks * 2 + aKu;
#pragma unroll
            for (int mb = 0; mb < 4; mb++) {
                uint32_t off = SWZ((uint32_t)((aRow + mb * 16) * 128 + ku * 16));
                ldsm_x4(aH_b + off, aH[mb][0], aH[mb][1], aH[mb][2], aH[mb][3]);
                ldsm_x4(aL_b + off, aL[mb][0], aL[mb][1], aL[mb][2], aL[mb][3]);
            }
            const int bku = ks * 2 + bKu;
#pragma unroll
            for (int nbp = 0; nbp < 2; nbp++) {
                uint32_t bh[4], bl[4];
                uint32_t boff = SWZ((uint32_t)((bRow + nbp * 16) * 128 + bku * 16));
                ldsm_x4(bH_b + boff, bh[0], bh[1], bh[2], bh[3]);
                ldsm_x4(bL_b + boff, bl[0], bl[1], bl[2], bl[3]);
#pragma unroll
                for (int h = 0; h < 2; h++) {
                    const int nb = nbp * 2 + h;
#pragma unroll
                    for (int mb = 0; mb < 4; mb++) {
                        mma_bf16(acc[mb][nb], aH[mb], bh[h * 2], bh[h * 2 + 1]);
                        mma_bf16(acc[mb][nb], aH[mb], bl[h * 2], bl[h * 2 + 1]);
                        mma_bf16(acc[mb][nb], aL[mb], bh[h * 2], bh[h * 2 + 1]);
                    }
                }
            }
        }
        __syncthreads();
    }

    // epilogue: regs -> smem stage -> coalesced GMEM with bias
    float* stage = (float*)smem;  // [128][132]
    {
        const int mr = warpM * 64 + (lane >> 2);
        const int nc = warpN * 32 + (lane & 3) * 2;
#pragma unroll
        for (int mb = 0; mb < 4; mb++) {
#pragma unroll
            for (int nb = 0; nb < 4; nb++) {
                float* p0 = &stage[(mr + mb * 16) * 132 + nc + nb * 8];
                float* p1 = &stage[(mr + mb * 16 + 8) * 132 + nc + nb * 8];
                p0[0] = acc[mb][nb][0];
                p0[1] = acc[mb][nb][1];
                p1[0] = acc[mb][nb][2];
                p1[1] = acc[mb][nb][3];
            }
        }
    }
    __syncthreads();

    const int colL = tid & 127;
    const float bz = bias[colBase + colL];
#pragma unroll
    for (int r0 = tid >> 7; r0 < 128; r0 += 2)
        C[(size_t)(rowBase + r0) * N + colBase + colL] = stage[r0 * 132 + colL] + bz;
}

// ---------------------------------------------------------------------------
// Launch. Output layout: preds | x_in_all | x_res_all | x_out_all
// ---------------------------------------------------------------------------
extern "C" void kernel_launch(void* const* d_in, const int* in_sizes, int n_in,
                              void* d_out, int out_size) {
    const float* inputs   = (const float*)d_in[0];
    const float* in_omega = (const float*)d_in[1];
    const float* in_gamma = (const float*)d_in[2];
    const float* in_alpha = (const float*)d_in[3];
    const float* proj_W   = (const float*)d_in[4];
    const float* proj_b   = (const float*)d_in[5];
    const float* res_om   = (const float*)d_in[6];
    const float* res_ga   = (const float*)d_in[7];
    const float* res_al   = (const float*)d_in[8];
    const float* out_om   = (const float*)d_in[9];
    const float* out_ga   = (const float*)d_in[10];
    const float* out_al   = (const float*)d_in[11];
    const float* read_W   = (const float*)d_in[12];
    const float* read_b   = (const float*)d_in[13];

    float* out = (float*)d_out;
    const size_t BTD = (size_t)B_ * T_ * D_;
    const size_t BTR = (size_t)B_ * T_ * R_;
    float* preds     = out;
    float* x_in_all  = out + BTD;
    float* x_res_all = out + 2 * BTD;
    float* x_out_all = out + 2 * BTD + BTR;

    void* p;
    cudaGetSymbolAddress(&p, g_proj);   float* proj = (float*)p;
    cudaGetSymbolAddress(&p, g_B2h);    __nv_bfloat16* B2h = (__nv_bfloat16*)p;
    cudaGetSymbolAddress(&p, g_B2l);    __nv_bfloat16* B2l = (__nv_bfloat16*)p;

    const int SMEM_BYTES = 2 * 65536;  // 131072
    cudaFuncSetAttribute(gemm_mma_split, cudaFuncAttributeMaxDynamicSharedMemorySize, SMEM_BYTES);

    // Phase 1: input oscillators
    k_input_osc<<<(B_ * D_) / 256, 256>>>(inputs, in_omega, in_gamma, in_alpha, x_in_all);

    // read_W split (for GEMM2 only)
    k_split_transpose<<<(R_ * D_ + 255) / 256, 256>>>(read_W, B2h, B2l, R_, D_);

    // Phase 2 (fp32, precision-critical): proj = x_in @ proj_W + proj_b
    {
        dim3 grid(R_ / 128, (B_ * T_) / 128);  // (16, 256)
        sgemm_bias_v2<<<grid, 256>>>(x_in_all, proj_W, proj_b, proj, B_ * T_, R_, D_);
    }

    // Phase 3: reservoir + output oscillators
    k_res_out_osc_v4<<<(B_ * R_ / 4) / 128, 128>>>((const float4*)proj,
                                                   (const float4*)res_om, (const float4*)res_ga,
                                                   (const float4*)res_al,
                                                   (const float4*)out_om, (const float4*)out_ga,
                                                   (const float4*)out_al,
                                                   (float4*)x_res_all, (float4*)x_out_all);

    // Phase 4 (split-bf16 tensor cores, tolerant): preds = x_out @ read_W + read_b
    {
        dim3 grid(D_ / 128, (B_ * T_) / 128);  // (1, 256)
        gemm_mma_split<<<grid, 256, SMEM_BYTES>>>(x_out_all, B2h, B2l, read_b, preds,
                                                  B_ * T_, D_, R_);
    }
}

// round 12
// speedup vs baseline: 1.4875x; 1.0842x over previous
#include <cuda_runtime.h>
#include <cuda_bf16.h>
#include <cstdint>

// Problem constants
#define B_  64
#define T_  512
#define D_  128
#define R_  2048
static constexpr float HSTEP = 0.5f;
static constexpr float CLAMP_ = 5.0f;

// Device scratch
__device__ float g_proj[(size_t)B_ * T_ * R_];                 // 256 MB
__device__ __nv_bfloat16 g_B2h[(size_t)D_ * R_];               // read_W bf16 planes [N=128, K=2048]
__device__ __nv_bfloat16 g_B2l[(size_t)D_ * R_];

__device__ __forceinline__ float clampf(float v) {
    return fminf(fmaxf(v, -CLAMP_), CLAMP_);
}

// ---------------------------------------------------------------------------
// Baseline-PTX helpers (bench ptxas targets sm_103: no 'a'-suffix features)
// ---------------------------------------------------------------------------
__device__ __forceinline__ uint32_t smem_u32(const void* p) {
    uint32_t a;
    asm("{ .reg .u64 t; cvta.to.shared.u64 t, %1; cvt.u32.u64 %0, t; }" : "=r"(a) : "l"(p));
    return a;
}
__device__ __forceinline__ void cp_async16(uint32_t dst, const void* src) {
    asm volatile("cp.async.ca.shared.global [%0], [%1], 16;" :: "r"(dst), "l"(src) : "memory");
}
#define CP_COMMIT() asm volatile("cp.async.commit_group;" ::: "memory")
#define CP_WAIT(n)  asm volatile("cp.async.wait_group %0;" :: "n"(n) : "memory")

__device__ __forceinline__ void ldsm_x4(uint32_t addr, uint32_t& r0, uint32_t& r1,
                                        uint32_t& r2, uint32_t& r3) {
    asm volatile("ldmatrix.sync.aligned.m8n8.x4.shared.b16 {%0,%1,%2,%3}, [%4];"
                 : "=r"(r0), "=r"(r1), "=r"(r2), "=r"(r3) : "r"(addr));
}
__device__ __forceinline__ void mma_bf16(float* c, const uint32_t* a, uint32_t b0, uint32_t b1) {
    asm volatile(
        "mma.sync.aligned.m16n8k16.row.col.f32.bf16.bf16.f32 "
        "{%0,%1,%2,%3}, {%4,%5,%6,%7}, {%8,%9}, {%0,%1,%2,%3};"
        : "+f"(c[0]), "+f"(c[1]), "+f"(c[2]), "+f"(c[3])
        : "r"(a[0]), "r"(a[1]), "r"(a[2]), "r"(a[3]), "r"(b0), "r"(b1));
}

#define SWZ(off) ((off) ^ (((off) >> 3) & 0x70))

// ---------------------------------------------------------------------------
// Phase 1: input oscillator recurrence. One thread per (b, d).
// ---------------------------------------------------------------------------
__global__ void k_input_osc(const float* __restrict__ inputs,
                            const float* __restrict__ omega,
                            const float* __restrict__ gamma_,
                            const float* __restrict__ alpha,
                            float* __restrict__ x_in_all) {
    int idx = blockIdx.x * blockDim.x + threadIdx.x;
    int d = idx % D_;
    int b = idx / D_;
    float om  = fabsf(omega[d]);
    float ga  = fabsf(gamma_[d]);
    float al  = alpha[d];
    float om2 = om * om;
    float g2  = 2.0f * ga;
    float x = 0.0f, y = 0.0f;
    const float* inp = inputs + (size_t)b * T_ * D_ + d;
    float*       out = x_in_all + (size_t)b * T_ * D_ + d;
#pragma unroll 4
    for (int t = 0; t < T_; t++) {
        float f  = inp[t * D_];
        float ac = al * f - g2 * y - om2 * x;
        float xn = clampf(x + HSTEP * y);
        float yn = clampf(y + HSTEP * ac);
        x = xn; y = yn;
        out[t * D_] = x;
    }
}

// ---------------------------------------------------------------------------
// Weight split (GEMM2 only): W [K,N] fp32 row-major -> Dh/Dl [N,K] bf16
// ---------------------------------------------------------------------------
__global__ void k_split_bf16(const float* __restrict__ W,
                             __nv_bfloat16* __restrict__ Dh,
                             __nv_bfloat16* __restrict__ Dl,
                             int K, int N) {
    int idx = blockIdx.x * blockDim.x + threadIdx.x;
    if (idx >= K * N) return;
    int n = idx % N, k = idx / N;
    float v = W[idx];
    __nv_bfloat16 h = __float2bfloat16_rn(v);
    __nv_bfloat16 l = __float2bfloat16_rn(v - __bfloat162float(h));
    Dh[(size_t)n * K + k] = h;
    Dl[(size_t)n * K + k] = l;
}

// ---------------------------------------------------------------------------
// Phase 3: reservoir + output oscillators, float2-vectorized over r.
// 65536 threads (2x the float4 version) -> higher occupancy, same arithmetic.
// ---------------------------------------------------------------------------
__global__ void k_res_out_osc_v2(const float2* __restrict__ proj,
                                 const float2* __restrict__ r_om, const float2* __restrict__ r_ga,
                                 const float2* __restrict__ r_al,
                                 const float2* __restrict__ o_om, const float2* __restrict__ o_ga,
                                 const float2* __restrict__ o_al,
                                 float2* __restrict__ x_res_all,
                                 float2* __restrict__ x_out_all) {
    constexpr int R2 = R_ / 2;  // 1024
    int idx = blockIdx.x * blockDim.x + threadIdx.x;
    int r2 = idx % R2;
    int b  = idx / R2;

    float2 romv = r_om[r2], rgav = r_ga[r2], ralv = r_al[r2];
    float2 oomv = o_om[r2], ogav = o_ga[r2], oalv = o_al[r2];
    float rom2[2], rg2[2], ral[2], oom2[2], og2[2], oal[2];
    {
        float v;
        v = fabsf(romv.x); rom2[0] = v * v; v = fabsf(romv.y); rom2[1] = v * v;
        rg2[0] = 2.0f * fabsf(rgav.x); rg2[1] = 2.0f * fabsf(rgav.y);
        ral[0] = ralv.x; ral[1] = ralv.y;
        v = fabsf(oomv.x); oom2[0] = v * v; v = fabsf(oomv.y); oom2[1] = v * v;
        og2[0] = 2.0f * fabsf(ogav.x); og2[1] = 2.0f * fabsf(ogav.y);
        oal[0] = oalv.x; oal[1] = oalv.y;
    }

    float xr[2] = {}, yr[2] = {}, xo[2] = {}, yo[2] = {};
    const float2* pp  = proj      + (size_t)b * T_ * R2 + r2;
    float2*       xra = x_res_all + (size_t)b * T_ * R2 + r2;
    float2*       xoa = x_out_all + (size_t)b * T_ * R2 + r2;

#pragma unroll 4
    for (int t = 0; t < T_; t++) {
        float2 fv = pp[t * R2];
        float f[2] = {fv.x, fv.y};
        float xrs[2], xos[2];
#pragma unroll
        for (int i = 0; i < 2; i++) {
            float acr = ral[i] * f[i] - rg2[i] * yr[i] - rom2[i] * xr[i];
            float xrn = clampf(xr[i] + HSTEP * yr[i]);
            float yrn = clampf(yr[i] + HSTEP * acr);
            xr[i] = xrn; yr[i] = yrn;
            float aco = oal[i] * xr[i] - og2[i] * yo[i] - oom2[i] * xo[i];
            float xon = clampf(xo[i] + HSTEP * yo[i]);
            float yon = clampf(yo[i] + HSTEP * aco);
            xo[i] = xon; yo[i] = yon;
            xrs[i] = xr[i]; xos[i] = xo[i];
        }
        xra[t * R2] = make_float2(xrs[0], xrs[1]);
        xoa[t * R2] = make_float2(xos[0], xos[1]);
    }
}

// ---------------------------------------------------------------------------
// GEMM1: fp32 SIMT (precision-critical — proj feeds a clamped chaotic
// recurrence whose decorrelation cliff sits at ~1e-6 proj deviation; only
// genuine fp32 FFMA stays under it). C[M,N] = A[M,K] @ B[K,N] + bias[N].
// BM=BN=128, BK=16, 256 threads, 8x8 microtile, double-buffered smem.
// ---------------------------------------------------------------------------
__global__ __launch_bounds__(256, 2) void sgemm_bias_v2(const float* __restrict__ A,
                                                        const float* __restrict__ Bm,
                                                        const float* __restrict__ bias,
                                                        float* __restrict__ C,
                                                        int M, int N, int K) {
    constexpr int BK = 16;
    __shared__ float As[2][BK][128 + 4];
    __shared__ float Bs[2][BK][128];

    const int tid = threadIdx.x;
    const int rowBase = blockIdx.y * 128;
    const int colBase = blockIdx.x * 128;

    const int aRow = tid >> 2;
    const int aCol = (tid & 3) * 4;
    const int bRow = tid >> 5;
    const int bCol = (tid & 31) * 4;

    const float* Aptr0 = A + (size_t)(rowBase + aRow) * K + aCol;
    const float* Aptr1 = Aptr0 + (size_t)64 * K;
    const float* Bptr0 = Bm + (size_t)bRow * N + colBase + bCol;
    const float* Bptr1 = Bptr0 + (size_t)8 * N;

    const int tm = (tid >> 4) * 8;
    const int tn = (tid & 15) * 8;

    float acc[8][8] = {};
    float4 pa0, pa1, pb0, pb1;

    pa0 = *(const float4*)(Aptr0);
    pa1 = *(const float4*)(Aptr1);
    pb0 = *(const float4*)(Bptr0);
    pb1 = *(const float4*)(Bptr1);
    {
        As[0][aCol + 0][aRow] = pa0.x;
        As[0][aCol + 1][aRow] = pa0.y;
        As[0][aCol + 2][aRow] = pa0.z;
        As[0][aCol + 3][aRow] = pa0.w;
        As[0][aCol + 0][aRow + 64] = pa1.x;
        As[0][aCol + 1][aRow + 64] = pa1.y;
        As[0][aCol + 2][aRow + 64] = pa1.z;
        As[0][aCol + 3][aRow + 64] = pa1.w;
        *(float4*)&Bs[0][bRow][bCol] = pb0;
        *(float4*)&Bs[0][bRow + 8][bCol] = pb1;
    }
    __syncthreads();

    int buf = 0;
    for (int k0 = 0; k0 < K; k0 += BK) {
        const int knext = k0 + BK;
        if (knext < K) {
            pa0 = *(const float4*)(Aptr0 + knext);
            pa1 = *(const float4*)(Aptr1 + knext);
            pb0 = *(const float4*)(Bptr0 + (size_t)knext * N);
            pb1 = *(const float4*)(Bptr1 + (size_t)knext * N);
        }
#pragma unroll
        for (int k = 0; k < BK; k++) {
            float4 ra0 = *(const float4*)&As[buf][k][tm];
            float4 ra1 = *(const float4*)&As[buf][k][tm + 4];
            float4 rb0 = *(const float4*)&Bs[buf][k][tn];
            float4 rb1 = *(const float4*)&Bs[buf][k][tn + 4];
            float ra[8] = {ra0.x, ra0.y, ra0.z, ra0.w, ra1.x, ra1.y, ra1.z, ra1.w};
            float rb[8] = {rb0.x, rb0.y, rb0.z, rb0.w, rb1.x, rb1.y, rb1.z, rb1.w};
#pragma unroll
            for (int i = 0; i < 8; i++)
#pragma unroll
                for (int j = 0; j < 8; j++) acc[i][j] += ra[i] * rb[j];
        }
        if (knext < K) {
            int nb = buf ^ 1;
            As[nb][aCol + 0][aRow] = pa0.x;
            As[nb][aCol + 1][aRow] = pa0.y;
            As[nb][aCol + 2][aRow] = pa0.z;
            As[nb][aCol + 3][aRow] = pa0.w;
            As[nb][aCol + 0][aRow + 64] = pa1.x;
            As[nb][aCol + 1][aRow + 64] = pa1.y;
            As[nb][aCol + 2][aRow + 64] = pa1.z;
            As[nb][aCol + 3][aRow + 64] = pa1.w;
            *(float4*)&Bs[nb][bRow][bCol] = pb0;
            *(float4*)&Bs[nb][bRow + 8][bCol] = pb1;
            __syncthreads();
            buf = nb;
        }
    }

    const int col0 = colBase + tn;
    float4 bz0 = *(const float4*)&bias[col0];
    float4 bz1 = *(const float4*)&bias[col0 + 4];
#pragma unroll
    for (int i = 0; i < 8; i++) {
        int row = rowBase + tm + i;
        float4 o0, o1;
        o0.x = acc[i][0] + bz0.x;
        o0.y = acc[i][1] + bz0.y;
        o0.z = acc[i][2] + bz0.z;
        o0.w = acc[i][3] + bz0.w;
        o1.x = acc[i][4] + bz1.x;
        o1.y = acc[i][5] + bz1.y;
        o1.z = acc[i][6] + bz1.z;
        o1.w = acc[i][7] + bz1.w;
        *(float4*)&C[(size_t)row * N + col0] = o0;
        *(float4*)&C[(size_t)row * N + col0 + 4] = o1;
    }
}

// ---------------------------------------------------------------------------
// GEMM2: split-bf16 mma, 3 terms (tolerant readout path) — r5-validated.
// C[M,N] = A[M,K](fp32) @ W + bias; W as bf16 hi/lo planes [N,K].
// CTA 128x128, K-chunks 64, double-buffered; D += Ah*Bh + Ah*Bl + Al*Bh.
// ---------------------------------------------------------------------------
__global__ __launch_bounds__(256) void gemm_mma_split(const float* __restrict__ A,
                                                      const __nv_bfloat16* __restrict__ Bh,
                                                      const __nv_bfloat16* __restrict__ Bl,
                                                      const float* __restrict__ bias,
                                                      float* __restrict__ C,
                                                      int M, int N, int K) {
    extern __shared__ char smem[];
    const int tid  = threadIdx.x;
    const int wid  = tid >> 5;
    const int lane = tid & 31;
    const uint32_t sb = smem_u32(smem);
    const int rowBase = blockIdx.y * 128;
    const int colBase = blockIdx.x * 128;
    const int NCHUNK = K >> 6;

    auto load_chunk = [&](int c, int s) {
        const int k0 = c << 6;
        char* Ah_s = smem + s * 65536;
        char* Al_s = Ah_s + 16384;
        const uint32_t bh_u = sb + s * 65536 + 32768;
        const uint32_t bl_u = bh_u + 16384;
#pragma unroll
        for (int i = 0; i < 4; i++) {
            int u = tid + 256 * i;
            int row = u >> 3;
            int kc = (u & 7) * 8;
            const float4* src = (const float4*)(A + (size_t)(rowBase + row) * K + k0 + kc);
            float4 v0 = src[0], v1 = src[1];
            float vv[8] = {v0.x, v0.y, v0.z, v0.w, v1.x, v1.y, v1.z, v1.w};
            __nv_bfloat16 h[8], l[8];
#pragma unroll
            for (int j = 0; j < 8; j++) {
                h[j] = __float2bfloat16_rn(vv[j]);
                l[j] = __float2bfloat16_rn(vv[j] - __bfloat162float(h[j]));
            }
            uint32_t off = SWZ((uint32_t)(row * 128 + kc * 2));
            *(uint4*)(Ah_s + off) = *(const uint4*)h;
            *(uint4*)(Al_s + off) = *(const uint4*)l;
        }
#pragma unroll
        for (int i = 0; i < 4; i++) {
            int ch = tid + 256 * i;
            int row = ch >> 3;
            int kc16 = ch & 7;
            uint32_t off = SWZ((uint32_t)(row * 128 + kc16 * 16));
            const char* sh = (const char*)(Bh + (size_t)(colBase + row) * K + k0) + kc16 * 16;
            const char* sl = (const char*)(Bl + (size_t)(colBase + row) * K + k0) + kc16 * 16;
            cp_async16(bh_u + off, sh);
            cp_async16(bl_u + off, sl);
        }
    };

    const int warpM = wid & 1;
    const int warpN = wid >> 1;
    const int g = lane >> 3;
    const int r = lane & 7;

    float acc[4][4][4] = {};

    const int aRow = warpM * 64 + (g & 1) * 8 + r;
    const int aKu  = (g >> 1);
    const int bRow = warpN * 32 + (g >> 1) * 8 + r;
    const int bKu  = (g & 1);

    load_chunk(0, 0);
    CP_COMMIT();

    for (int c = 0; c < NCHUNK; c++) {
        const int s = c & 1;
        if (c + 1 < NCHUNK) {
            load_chunk(c + 1, s ^ 1);
            CP_COMMIT();
            CP_WAIT(1);
        } else {
            CP_WAIT(0);
        }
        __syncthreads();

        const uint32_t aH_b = sb + s * 65536;
        const uint32_t aL_b = aH_b + 16384;
        const uint32_t bH_b = aH_b + 32768;
        const uint32_t bL_b = aH_b + 49152;

#pragma unroll
        for (int ks = 0; ks < 4; ks++) {
            uint32_t aH[4][4], aL[4][4];
            const int ku = ks * 2 + aKu;
#pragma unroll
            for (int mb = 0; mb < 4; mb++) {
                uint32_t off = SWZ((uint32_t)((aRow + mb * 16) * 128 + ku * 16));
                ldsm_x4(aH_b + off, aH[mb][0], aH[mb][1], aH[mb][2], aH[mb][3]);
                ldsm_x4(aL_b + off, aL[mb][0], aL[mb][1], aL[mb][2], aL[mb][3]);
            }
            const int bku = ks * 2 + bKu;
#pragma unroll
            for (int nbp = 0; nbp < 2; nbp++) {
                uint32_t bh[4], bl[4];
                uint32_t boff = SWZ((uint32_t)((bRow + nbp * 16) * 128 + bku * 16));
                ldsm_x4(bH_b + boff, bh[0], bh[1], bh[2], bh[3]);
                ldsm_x4(bL_b + boff, bl[0], bl[1], bl[2], bl[3]);
#pragma unroll
                for (int h = 0; h < 2; h++) {
                    const int nb = nbp * 2 + h;
#pragma unroll
                    for (int mb = 0; mb < 4; mb++) {
                        mma_bf16(acc[mb][nb], aH[mb], bh[h * 2], bh[h * 2 + 1]);
                        mma_bf16(acc[mb][nb], aH[mb], bl[h * 2], bl[h * 2 + 1]);
                        mma_bf16(acc[mb][nb], aL[mb], bh[h * 2], bh[h * 2 + 1]);
                    }
                }
            }
        }
        __syncthreads();
    }

    // epilogue: regs -> smem stage -> coalesced GMEM with bias
    float* stage = (float*)smem;  // [128][132]
    {
        const int mr = warpM * 64 + (lane >> 2);
        const int nc = warpN * 32 + (lane & 3) * 2;
#pragma unroll
        for (int mb = 0; mb < 4; mb++) {
#pragma unroll
            for (int nb = 0; nb < 4; nb++) {
                float* p0 = &stage[(mr + mb * 16) * 132 + nc + nb * 8];
                float* p1 = &stage[(mr + mb * 16 + 8) * 132 + nc + nb * 8];
                p0[0] = acc[mb][nb][0];
                p0[1] = acc[mb][nb][1];
                p1[0] = acc[mb][nb][2];
                p1[1] = acc[mb][nb][3];
            }
        }
    }
    __syncthreads();

    const int colL = tid & 127;
    const float bz = bias[colBase + colL];
#pragma unroll
    for (int r0 = tid >> 7; r0 < 128; r0 += 2)
        C[(size_t)(rowBase + r0) * N + colBase + colL] = stage[r0 * 132 + colL] + bz;
}

// ---------------------------------------------------------------------------
// Launch. Output layout: preds | x_in_all | x_res_all | x_out_all
// ---------------------------------------------------------------------------
extern "C" void kernel_launch(void* const* d_in, const int* in_sizes, int n_in,
                              void* d_out, int out_size) {
    const float* inputs   = (const float*)d_in[0];
    const float* in_omega = (const float*)d_in[1];
    const float* in_gamma = (const float*)d_in[2];
    const float* in_alpha = (const float*)d_in[3];
    const float* proj_W   = (const float*)d_in[4];
    const float* proj_b   = (const float*)d_in[5];
    const float* res_om   = (const float*)d_in[6];
    const float* res_ga   = (const float*)d_in[7];
    const float* res_al   = (const float*)d_in[8];
    const float* out_om   = (const float*)d_in[9];
    const float* out_ga   = (const float*)d_in[10];
    const float* out_al   = (const float*)d_in[11];
    const float* read_W   = (const float*)d_in[12];
    const float* read_b   = (const float*)d_in[13];

    float* out = (float*)d_out;
    const size_t BTD = (size_t)B_ * T_ * D_;
    const size_t BTR = (size_t)B_ * T_ * R_;
    float* preds     = out;
    float* x_in_all  = out + BTD;
    float* x_res_all = out + 2 * BTD;
    float* x_out_all = out + 2 * BTD + BTR;

    void* p;
    cudaGetSymbolAddress(&p, g_proj);   float* proj = (float*)p;
    cudaGetSymbolAddress(&p, g_B2h);    __nv_bfloat16* B2h = (__nv_bfloat16*)p;
    cudaGetSymbolAddress(&p, g_B2l);    __nv_bfloat16* B2l = (__nv_bfloat16*)p;

    const int SMEM_G2 = 2 * 65536;  // 131072 (double-buffered)
    cudaFuncSetAttribute(gemm_mma_split, cudaFuncAttributeMaxDynamicSharedMemorySize, SMEM_G2);

    // Phase 1: input oscillators
    k_input_osc<<<(B_ * D_) / 256, 256>>>(inputs, in_omega, in_gamma, in_alpha, x_in_all);

    // read_W split (for GEMM2 only)
    k_split_bf16<<<(R_ * D_ + 255) / 256, 256>>>(read_W, B2h, B2l, R_, D_);

    // Phase 2 (fp32 SIMT, precision-critical): proj = x_in @ proj_W + proj_b
    {
        dim3 grid(R_ / 128, (B_ * T_) / 128);  // (16, 256)
        sgemm_bias_v2<<<grid, 256>>>(x_in_all, proj_W, proj_b, proj, B_ * T_, R_, D_);
    }

    // Phase 3: reservoir + output oscillators (float2, 65536 threads)
    k_res_out_osc_v2<<<(B_ * R_ / 2) / 256, 256>>>((const float2*)proj,
                                                   (const float2*)res_om, (const float2*)res_ga,
                                                   (const float2*)res_al,
                                                   (const float2*)out_om, (const float2*)out_ga,
                                                   (const float2*)out_al,
                                                   (float2*)x_res_all, (float2*)x_out_all);

    // Phase 4 (split-bf16 tensor cores, tolerant): preds = x_out @ read_W + read_b
    {
        dim3 grid(D_ / 128, (B_ * T_) / 128);  // (1, 256)
        gemm_mma_split<<<grid, 256, SMEM_G2>>>(x_out_all, B2h, B2l, read_b, preds,
                                               B_ * T_, D_, R_);
    }
}